// round 1
// baseline (speedup 1.0000x reference)
#include <cuda_runtime.h>
#include <cstdint>

// Problem shape (fixed by setup_inputs): B=64, T=2000, V=256, S=200, L=2S+1=401
#define NEGV -1e30f
#define VDIM 256
#define SMAX 200
#define LMAX (2 * SMAX + 1)   // 401
#define BMAX 64
#define TMAX 2000

// Scratch for per-(b,t) logsumexp. Static device global: no allocation.
__device__ float g_lse[BMAX * TMAX];

// ---------------------------------------------------------------------------
// Kernel 1: LSE over V=256 per row. One warp per row, 2x float4 per lane.
// ---------------------------------------------------------------------------
__global__ void lse_kernel(const float* __restrict__ logits, int rows)
{
    int warp = (blockIdx.x * blockDim.x + threadIdx.x) >> 5;
    int lane = threadIdx.x & 31;
    if (warp >= rows) return;

    const float4* row4 = reinterpret_cast<const float4*>(logits + (size_t)warp * VDIM);
    float4 a = row4[lane];        // elems [4*lane, 4*lane+4)
    float4 b = row4[lane + 32];   // elems [128+4*lane, ...)

    float m = fmaxf(fmaxf(fmaxf(a.x, a.y), fmaxf(a.z, a.w)),
                    fmaxf(fmaxf(b.x, b.y), fmaxf(b.z, b.w)));
    #pragma unroll
    for (int o = 16; o; o >>= 1)
        m = fmaxf(m, __shfl_xor_sync(0xFFFFFFFFu, m, o));

    float s = expf(a.x - m) + expf(a.y - m) + expf(a.z - m) + expf(a.w - m)
            + expf(b.x - m) + expf(b.y - m) + expf(b.z - m) + expf(b.w - m);
    #pragma unroll
    for (int o = 16; o; o >>= 1)
        s += __shfl_xor_sync(0xFFFFFFFFu, s, o);

    if (lane == 0) g_lse[warp] = m + logf(s);
}

// ---------------------------------------------------------------------------
// Kernel 2: CTC alpha recursion. One block per batch row, 512 threads.
// alpha double-buffered in shared; 2 syncs per timestep; next row prefetched.
// ---------------------------------------------------------------------------
__global__ __launch_bounds__(512, 1)
void ctc_alpha_kernel(const float* __restrict__ logits,
                      const int*  __restrict__ targets,
                      const int*  __restrict__ logits_lengths,
                      const int*  __restrict__ targets_lengths,
                      float* __restrict__ out,
                      int T, int S)
{
    const int b   = blockIdx.x;
    const int tid = threadIdx.x;
    const int L   = 2 * S + 1;

    __shared__ float         sh_row[VDIM];
    __shared__ int           ext[LMAX];
    __shared__ unsigned char skipf[LMAX];
    __shared__ float         alpha[2][LMAX + 2];

    // Extended label sequence: [blank, t0, blank, t1, ..., blank]
    for (int s = tid; s < L; s += blockDim.x)
        ext[s] = (s & 1) ? targets[b * S + (s >> 1)] : 0;

    // alpha init (state s lives at index s+2; [0],[1] are permanent NEG pads)
    if (tid < 2) { alpha[0][tid] = NEGV; alpha[1][tid] = NEGV; }
    for (int s = tid; s < L; s += blockDim.x)
        alpha[0][s + 2] = (s == 0) ? 0.0f : NEGV;
    __syncthreads();

    // skip transition allowed iff ext[s] != blank and ext[s] != ext[s-2]
    for (int s = tid; s < L; s += blockDim.x)
        skipf[s] = (unsigned char)((s >= 2) && (ext[s] != 0) && (ext[s] != ext[s - 2]));

    const int len = logits_lengths[b];
    const float* __restrict__ rowp = logits + (size_t)b * T * VDIM;
    const float* __restrict__ lsep = g_lse + (size_t)b * T;

    // prefetch t=0
    float r  = (tid < VDIM) ? rowp[tid] : 0.0f;
    float lz = lsep[0];

    int cur = 0;
    __syncthreads();   // skipf + ext visible; alpha init visible

    for (int t = 0; t < len; ++t) {
        if (tid < VDIM) sh_row[tid] = r;
        const float lse_t = lz;
        __syncthreads();

        // prefetch next row while this step's math runs
        if (t + 1 < len) {
            if (tid < VDIM) r = __ldg(&rowp[(size_t)(t + 1) * VDIM + tid]);
            lz = __ldg(&lsep[t + 1]);
        }

        if (tid < L) {
            const float lp = sh_row[ext[tid]] - lse_t;
            const float a1 = alpha[cur][tid + 2];
            const float a2 = alpha[cur][tid + 1];
            const float a3 = skipf[tid] ? alpha[cur][tid] : NEGV;
            float m  = fmaxf(a1, fmaxf(a2, a3));
            float ss = expf(a1 - m) + expf(a2 - m) + expf(a3 - m);
            alpha[cur ^ 1][tid + 2] = m + logf(ss) + lp;
        }
        __syncthreads();
        cur ^= 1;
    }

    if (tid == 0) {
        const int tl = targets_lengths[b];
        const float l1 = alpha[cur][2 * tl - 1 + 2];
        const float l2 = alpha[cur][2 * tl + 2];
        const float m  = fmaxf(l1, l2);
        out[b] = -(m + logf(expf(l1 - m) + expf(l2 - m)));
    }
}

// ---------------------------------------------------------------------------
// Launch
// ---------------------------------------------------------------------------
extern "C" void kernel_launch(void* const* d_in, const int* in_sizes, int n_in,
                              void* d_out, int out_size)
{
    const float* logits         = (const float*)d_in[0];
    const int*   targets        = (const int*)  d_in[1];
    const int*   logits_lengths = (const int*)  d_in[2];
    const int*   targets_lengths= (const int*)  d_in[3];
    float*       out            = (float*)      d_out;

    const int B = in_sizes[2];                       // 64
    const int S = in_sizes[1] / B;                   // 200
    const int T = in_sizes[0] / (B * VDIM);          // 2000
    const int rows = B * T;

    // Kernel 1: LSE. 8 warps per 256-thread block.
    const int warps_per_block = 8;
    const int blocks1 = (rows + warps_per_block - 1) / warps_per_block;
    lse_kernel<<<blocks1, warps_per_block * 32>>>(logits, rows);

    // Kernel 2: recursion. One block per batch row.
    ctc_alpha_kernel<<<B, 512>>>(logits, targets, logits_lengths,
                                 targets_lengths, out, T, S);
}

// round 2
// speedup vs baseline: 2.0159x; 2.0159x over previous
#include <cuda_runtime.h>
#include <cstdint>

// Shape (fixed by setup_inputs): B=64, T=2000, V=256, S=200, L=401
#define NEGV -1e30f
#define VDIM 256
#define SMAX 200
#define LMAX (2 * SMAX + 1)   // 401
#define BMAX 64
#define TMAX 2000
#define NTHR 416              // 13 full warps >= L
#define NWARP 13

// Per-(b,t) logsumexp scratch. Static device global: no allocation.
__device__ float g_lse[BMAX * TMAX];

// ---------------------------------------------------------------------------
// Kernel 1: LSE over V=256 per (b,t) row. One warp per row, 2x float4/lane.
// ---------------------------------------------------------------------------
__global__ void lse_kernel(const float* __restrict__ logits, int rows)
{
    int warp = (blockIdx.x * blockDim.x + threadIdx.x) >> 5;
    int lane = threadIdx.x & 31;
    if (warp >= rows) return;

    const float4* row4 = reinterpret_cast<const float4*>(logits + (size_t)warp * VDIM);
    float4 a = row4[lane];
    float4 b = row4[lane + 32];

    float m = fmaxf(fmaxf(fmaxf(a.x, a.y), fmaxf(a.z, a.w)),
                    fmaxf(fmaxf(b.x, b.y), fmaxf(b.z, b.w)));
    #pragma unroll
    for (int o = 16; o; o >>= 1)
        m = fmaxf(m, __shfl_xor_sync(0xFFFFFFFFu, m, o));

    float s = __expf(a.x - m) + __expf(a.y - m) + __expf(a.z - m) + __expf(a.w - m)
            + __expf(b.x - m) + __expf(b.y - m) + __expf(b.z - m) + __expf(b.w - m);
    #pragma unroll
    for (int o = 16; o; o >>= 1)
        s += __shfl_xor_sync(0xFFFFFFFFu, s, o);

    if (lane == 0) g_lse[warp] = m + __logf(s);
}

// ---------------------------------------------------------------------------
// Kernel 2: CTC alpha recursion on UNNORMALIZED logits.
//   - alpha in registers, neighbors via shfl, warp boundaries via 2-float
//     double-buffered shared tails -> ONE __syncthreads per timestep.
//   - logits row staged through a depth-3 cp.async ring (4 stages).
//   - normalization applied once at the end: loss = sum(lse) - LAE(finals).
// ---------------------------------------------------------------------------
__global__ __launch_bounds__(NTHR, 1)
void ctc_alpha_kernel(const float* __restrict__ logits,
                      const int*  __restrict__ targets,
                      const int*  __restrict__ logits_lengths,
                      const int*  __restrict__ targets_lengths,
                      float* __restrict__ out,
                      int T, int S)
{
    const int b    = blockIdx.x;
    const int tid  = threadIdx.x;
    const int lane = tid & 31;
    const int w    = tid >> 5;
    const int L    = 2 * S + 1;

    __shared__ float sh_row[4][VDIM];        // cp.async ring, stage = t & 3
    __shared__ float sh_tail[2][NWARP][2];   // last-2 alphas per warp, dbl-buffered
    __shared__ float sh_fin[2];
    __shared__ float sh_red[NTHR];

    // Per-thread state metadata (registers only).
    int label = 0, skip = 0;
    if (tid < L && (tid & 1)) {
        label = __ldg(&targets[b * S + (tid >> 1)]);
        if (tid >= 2)
            skip = (label != __ldg(&targets[b * S + ((tid - 2) >> 1)]));
    }
    float a = (tid == 0) ? 0.0f : NEGV;

    // Init boundary tails (both buffers) to NEG.
    if (tid < 2 * NWARP * 2) ((float*)sh_tail)[tid] = NEGV;

    const int len = logits_lengths[b];
    const float* __restrict__ rowp = logits + (size_t)b * T * VDIM;

    // cp.async prologue: stages for t = 0,1,2 (threads 0..63, 16B each).
    uint32_t s_base = (uint32_t)__cvta_generic_to_shared(&sh_row[0][0]);
    if (tid < 64) {
        #pragma unroll
        for (int p = 0; p < 3; ++p) {
            uint32_t dst = s_base + (uint32_t)(p * VDIM + tid * 4) * 4u;
            const float* src = rowp + (size_t)p * VDIM + tid * 4;
            asm volatile("cp.async.ca.shared.global [%0], [%1], 16;\n"
                         :: "r"(dst), "l"(src));
            asm volatile("cp.async.commit_group;\n");
        }
    }

    int buf = 0;
    for (int t = 0; t < len; ++t) {
        // Stage t guaranteed complete once <=2 groups pending.
        asm volatile("cp.async.wait_group 2;\n" ::: "memory");
        __syncthreads();   // stage t visible; prev-iter tails visible

        float tb0 = NEGV, tb1 = NEGV;
        if (lane < 2 && w > 0) {
            tb0 = sh_tail[buf][w - 1][0];   // alpha[32w-2]
            tb1 = sh_tail[buf][w - 1][1];   // alpha[32w-1]
        }
        const float lp = sh_row[t & 3][label];

        const float a1 = a;
        float a2 = __shfl_up_sync(0xFFFFFFFFu, a, 1);
        float a3 = __shfl_up_sync(0xFFFFFFFFu, a, 2);
        if (lane == 0)      { a2 = tb1; a3 = tb0; }
        else if (lane == 1) { a3 = tb1; }
        if (!skip) a3 = NEGV;

        float m  = fmaxf(a1, fmaxf(a2, a3));
        float ss = __expf(a1 - m) + __expf(a2 - m) + __expf(a3 - m);
        a = m + __logf(ss) + lp;

        if (lane >= 30) sh_tail[buf ^ 1][w][lane - 30] = a;

        // Prefetch row t+3 into stage (t+3)&3 == (t-1)&3 (free: all readers of
        // that stage finished before this iteration's barrier).
        if (tid < 64) {
            const int tn = t + 3;
            if (tn < len) {
                uint32_t dst = s_base + (uint32_t)(((tn & 3) * VDIM + tid * 4)) * 4u;
                const float* src = rowp + (size_t)tn * VDIM + tid * 4;
                asm volatile("cp.async.ca.shared.global [%0], [%1], 16;\n"
                             :: "r"(dst), "l"(src));
            }
            asm volatile("cp.async.commit_group;\n");
        }
        buf ^= 1;
    }

    // ---- epilogue: finals + masked LSE sum + combine ----
    const int tl = __ldg(&targets_lengths[b]);
    if (tid == 2 * tl - 1) sh_fin[0] = a;
    if (tid == 2 * tl)     sh_fin[1] = a;

    float ssum = 0.0f;
    const float* __restrict__ lsep = g_lse + (size_t)b * T;
    for (int t = tid; t < len; t += NTHR) ssum += lsep[t];
    sh_red[tid] = ssum;
    __syncthreads();
    #pragma unroll
    for (int o = 256; o > 0; o >>= 1) {
        if (tid < o && tid + o < NTHR) sh_red[tid] += sh_red[tid + o];
        __syncthreads();
    }

    if (tid == 0) {
        const float f1 = sh_fin[0], f2 = sh_fin[1];
        const float mm = fmaxf(f1, f2);
        // loss = sum(lse) - logaddexp(f1, f2)
        out[b] = sh_red[0] - (mm + __logf(__expf(f1 - mm) + __expf(f2 - mm)));
    }
}

// ---------------------------------------------------------------------------
// Launch
// ---------------------------------------------------------------------------
extern "C" void kernel_launch(void* const* d_in, const int* in_sizes, int n_in,
                              void* d_out, int out_size)
{
    const float* logits          = (const float*)d_in[0];
    const int*   targets         = (const int*)  d_in[1];
    const int*   logits_lengths  = (const int*)  d_in[2];
    const int*   targets_lengths = (const int*)  d_in[3];
    float*       out             = (float*)      d_out;

    const int B = in_sizes[2];               // 64
    const int S = in_sizes[1] / B;           // 200
    const int T = in_sizes[0] / (B * VDIM);  // 2000
    const int rows = B * T;

    const int warps_per_block = 8;
    const int blocks1 = (rows + warps_per_block - 1) / warps_per_block;
    lse_kernel<<<blocks1, warps_per_block * 32>>>(logits, rows);

    ctc_alpha_kernel<<<B, NTHR>>>(logits, targets, logits_lengths,
                                  targets_lengths, out, T, S);
}

// round 4
// speedup vs baseline: 2.7802x; 1.3791x over previous
#include <cuda_runtime.h>
#include <cstdint>

// Shape (fixed by setup_inputs): B=64, T=2000, V=256, S=200, L=401
#define NEG2 -1e30f
#define VDIM 256
#define SMAX 200
#define BMAX 64
#define TMAX 2000
#define NTHR 224              // 7 warps; thread i owns states (2i, 2i+1)
#define NWARP 7
#define NSTAGE 8              // cp.async ring stages
#define INVLN2 1.4426950408889634f
#define LN2F   0.6931471805599453f

// Per-(b,t) logsumexp scratch. Static device global: no allocation.
__device__ float g_lse[BMAX * TMAX];

__device__ __forceinline__ float ex2f(float x) {
    float y; asm("ex2.approx.f32 %0, %1;" : "=f"(y) : "f"(x)); return y;
}
__device__ __forceinline__ float lg2f(float x) {
    float y; asm("lg2.approx.f32 %0, %1;" : "=f"(y) : "f"(x)); return y;
}

// ---------------------------------------------------------------------------
// Kernel 1: LSE over V=256 per (b,t) row. One warp per row, 2x float4/lane.
// ---------------------------------------------------------------------------
__global__ void lse_kernel(const float* __restrict__ logits, int rows)
{
    int warp = (blockIdx.x * blockDim.x + threadIdx.x) >> 5;
    int lane = threadIdx.x & 31;
    if (warp >= rows) return;

    const float4* row4 = reinterpret_cast<const float4*>(logits + (size_t)warp * VDIM);
    float4 a = row4[lane];
    float4 b = row4[lane + 32];

    float m = fmaxf(fmaxf(fmaxf(a.x, a.y), fmaxf(a.z, a.w)),
                    fmaxf(fmaxf(b.x, b.y), fmaxf(b.z, b.w)));
    #pragma unroll
    for (int o = 16; o; o >>= 1)
        m = fmaxf(m, __shfl_xor_sync(0xFFFFFFFFu, m, o));

    float s = __expf(a.x - m) + __expf(a.y - m) + __expf(a.z - m) + __expf(a.w - m)
            + __expf(b.x - m) + __expf(b.y - m) + __expf(b.z - m) + __expf(b.w - m);
    #pragma unroll
    for (int o = 16; o; o >>= 1)
        s += __shfl_xor_sync(0xFFFFFFFFu, s, o);

    if (lane == 0) g_lse[warp] = m + __logf(s);
}

// ---------------------------------------------------------------------------
// Kernel 2: log2-domain CTC alpha recursion, 2 states per thread.
//   Thread i owns A0 = alpha[2i] (blank) and A1 = alpha[2i+1] (label).
//   Blank states: no skip, shared emission logit[t][0].
//     A0' = LAE2(A0, pA1) + eb
//     A1' = LAE3(A1, A0, skip ? pA1 : NEG) + e1     (all OLD values)
//   where pA1 = neighbor thread's A1 (one shfl; one tail float per warp).
//   Unnormalized logits; loss = sum(lse) - ln2*LAE2(f1, f2).
// ---------------------------------------------------------------------------
__global__ __launch_bounds__(NTHR, 1)
void ctc_alpha_kernel(const float* __restrict__ logits,
                      const int*  __restrict__ targets,
                      const int*  __restrict__ logits_lengths,
                      const int*  __restrict__ targets_lengths,
                      float* __restrict__ out,
                      int T, int S)
{
    const int b    = blockIdx.x;
    const int tid  = threadIdx.x;
    const int lane = tid & 31;
    const int w    = tid >> 5;

    __shared__ float sh_row[NSTAGE][VDIM];   // cp.async ring
    __shared__ float sh_tail[2][NWARP];      // A1 of lane 31 per warp, dbl-buffered
    __shared__ float sh_fin[2];
    __shared__ float sh_red[NTHR];

    // Thread i: odd state 2i+1 has label targets[i], skip iff targets[i]!=targets[i-1].
    int label1 = 0, skip1 = 0;
    if (tid < S) {
        label1 = __ldg(&targets[b * S + tid]);
        if (tid >= 1)
            skip1 = (label1 != __ldg(&targets[b * S + tid - 1]));
    }

    float A0 = (tid == 0) ? 0.0f : NEG2;   // log2 domain
    float A1 = NEG2;

    if (tid < 2 * NWARP) ((float*)sh_tail)[tid] = NEG2;

    const int len = logits_lengths[b];
    const float* __restrict__ rowp = logits + (size_t)b * T * VDIM;

    // cp.async prologue: stages 0..5 (threads 0..63, 16B each).
    uint32_t s_base = (uint32_t)__cvta_generic_to_shared(&sh_row[0][0]);
    if (tid < 64) {
        #pragma unroll
        for (int p = 0; p < 6; ++p) {
            uint32_t dst = s_base + (uint32_t)(p * VDIM + tid * 4) * 4u;
            const float* src = rowp + (size_t)p * VDIM + tid * 4;
            asm volatile("cp.async.ca.shared.global [%0], [%1], 16;\n"
                         :: "r"(dst), "l"(src));
            asm volatile("cp.async.commit_group;\n");
        }
        asm volatile("cp.async.wait_group 5;\n" ::: "memory");  // stage 0 done
    }
    __syncthreads();

    // Emissions for t=0 (log2 units), prefetched.
    float eb = sh_row[0][0]      * INVLN2;
    float e1 = sh_row[0][label1] * INVLN2;

    int buf = 0;
    for (int t = 0; t < len; ++t) {
        if (tid < 64)
            asm volatile("cp.async.wait_group 4;\n" ::: "memory"); // stage t+1 done
        __syncthreads();   // tails + stage t+1 visible

        // Neighbor's odd-state alpha (state 2i-1).
        float pA1 = __shfl_up_sync(0xFFFFFFFFu, A1, 1);
        if (lane == 0) pA1 = (w > 0) ? sh_tail[buf][w - 1] : NEG2;

        // Blank state update (2-term).
        float m0 = fmaxf(A0, pA1);
        float n0 = m0 + lg2f(ex2f(A0 - m0) + ex2f(pA1 - m0)) + eb;

        // Label state update (3-term), from OLD values.
        float s3 = skip1 ? pA1 : NEG2;
        float m1 = fmaxf(fmaxf(A1, A0), s3);
        float n1 = m1 + lg2f(ex2f(A1 - m1) + ex2f(A0 - m1) + ex2f(s3 - m1)) + e1;

        A0 = n0;
        A1 = n1;

        if (lane == 31) sh_tail[buf ^ 1][w] = A1;

        // Prefetch emissions for t+1 (stage t+1 resident; off critical path).
        eb = sh_row[(t + 1) & (NSTAGE - 1)][0]      * INVLN2;
        e1 = sh_row[(t + 1) & (NSTAGE - 1)][label1] * INVLN2;

        // Issue stage t+6; commit unconditionally to keep group accounting.
        if (tid < 64) {
            const int tn = t + 6;
            if (tn < len) {
                uint32_t dst = s_base +
                    (uint32_t)(((tn & (NSTAGE - 1)) * VDIM + tid * 4)) * 4u;
                const float* src = rowp + (size_t)tn * VDIM + tid * 4;
                asm volatile("cp.async.ca.shared.global [%0], [%1], 16;\n"
                             :: "r"(dst), "l"(src));
            }
            asm volatile("cp.async.commit_group;\n");
        }
        buf ^= 1;
    }

    // ---- epilogue ----
    const int tl = __ldg(&targets_lengths[b]);
    if (tid == tl - 1) sh_fin[0] = A1;   // state 2*tl - 1
    if (tid == tl)     sh_fin[1] = A0;   // state 2*tl

    float ssum = 0.0f;
    const float* __restrict__ lsep = g_lse + (size_t)b * T;
    for (int t = tid; t < len; t += NTHR) ssum += lsep[t];
    sh_red[tid] = ssum;
    __syncthreads();
    #pragma unroll
    for (int o = 128; o > 0; o >>= 1) {
        if (tid < o && tid + o < NTHR) sh_red[tid] += sh_red[tid + o];
        __syncthreads();
    }

    if (tid == 0) {
        const float f1 = sh_fin[0], f2 = sh_fin[1];  // log2 units
        const float mm = fmaxf(f1, f2);
        const float lae = mm + lg2f(ex2f(f1 - mm) + ex2f(f2 - mm));
        out[b] = sh_red[0] - LN2F * lae;
    }
}

// ---------------------------------------------------------------------------
// Launch
// ---------------------------------------------------------------------------
extern "C" void kernel_launch(void* const* d_in, const int* in_sizes, int n_in,
                              void* d_out, int out_size)
{
    const float* logits          = (const float*)d_in[0];
    const int*   targets         = (const int*)  d_in[1];
    const int*   logits_lengths  = (const int*)  d_in[2];
    const int*   targets_lengths = (const int*)  d_in[3];
    float*       out             = (float*)      d_out;

    const int B = in_sizes[2];               // 64
    const int S = in_sizes[1] / B;           // 200
    const int T = in_sizes[0] / (B * VDIM);  // 2000
    const int rows = B * T;

    const int warps_per_block = 8;
    const int blocks1 = (rows + warps_per_block - 1) / warps_per_block;
    lse_kernel<<<blocks1, warps_per_block * 32>>>(logits, rows);

    ctc_alpha_kernel<<<B, NTHR>>>(logits, targets, logits_lengths,
                                  targets_lengths, out, T, S);
}